// round 8
// baseline (speedup 1.0000x reference)
#include <cuda_runtime.h>
#include <cuda_bf16.h>
#include <cstdint>

// Problem: B=256, N=64, d=64. Outputs concatenated: alphas [B,N,N,1] then value [B,N,N,64].
constexpr int Bn = 256;
constexpr int Nn = 64;
constexpr int Dn = 64;
constexpr float NEG_SLOPE = 0.01f;

// dynamic smem layout (bytes)
constexpr int OFF_WB  = 0;                       // 64 f32
constexpr int OFF_AW  = 256;                     // 64 f32
constexpr int OFF_LOG = 512;                     // 256 f32 (4 i's x 64 logits)
constexpr int OFF_XI  = 1536;                    // 4 i-rows natural fp32, stride 72: 1152 B
constexpr int OFF_SA  = 2688;                    // E frag table bf16 hi/lo (swizzled): 16384
constexpr int OFF_SBI = OFF_SA + 16384;          // B_i tables (W*x_i), 2 x 16KB ping-pong: 32768
constexpr int SMEM_TOTAL = OFF_SBI + 32768;      // 51840 B

static __device__ __forceinline__ void mma_bf16(float* c, const uint32_t* a, const uint32_t* b) {
    asm volatile(
        "mma.sync.aligned.m16n8k16.row.col.f32.bf16.bf16.f32 "
        "{%0,%1,%2,%3}, {%4,%5,%6,%7}, {%8,%9}, {%0,%1,%2,%3};"
        : "+f"(c[0]), "+f"(c[1]), "+f"(c[2]), "+f"(c[3])
        : "r"(a[0]), "r"(a[1]), "r"(a[2]), "r"(a[3]), "r"(b[0]), "r"(b[1]));
}

// split fp32 pair -> packed bf16x2 hi and bf16x2 lo
static __device__ __forceinline__ void split2(float a, float b, uint32_t& hi, uint32_t& lo) {
    __nv_bfloat16 ha = __float2bfloat16_rn(a);
    __nv_bfloat16 hb = __float2bfloat16_rn(b);
    float ra = a - __bfloat162float(ha);
    float rb = b - __bfloat162float(hb);
    __nv_bfloat162 h; h.x = ha; h.y = hb;
    __nv_bfloat162 l; l.x = __float2bfloat16_rn(ra); l.y = __float2bfloat16_rn(rb);
    hi = *reinterpret_cast<uint32_t*>(&h);
    lo = *reinterpret_cast<uint32_t*>(&l);
}

static __device__ __forceinline__ void stcs4(float* p, float4 v) {
    asm volatile("st.global.cs.v4.f32 [%0], {%1,%2,%3,%4};"
                 :: "l"(p), "f"(v.x), "f"(v.y), "f"(v.z), "f"(v.w) : "memory");
}

// swizzled byte offset of 16B unit (row*4+q) inside ks-block of a frag table.
static __device__ __forceinline__ uint32_t swzoff(int j, int q, int ks) {
    uint32_t u = (uint32_t)(j * 4 + q);
    uint32_t t = (((uint32_t)j & 3u) << 1) | (((uint32_t)ks >> 1) & 1u);
    return ((uint32_t)ks << 12) + ((u ^ t) << 4);
}

// pack 4 fp32 product vectors (one 16-d slab) into the frag table at row jr, block ks
static __device__ __forceinline__ void pack_slab(char* table, int jr, int ks, const float4* v4) {
    #pragma unroll
    for (int qq = 0; qq < 4; qq++) {
        float4 va = v4[qq >> 1];
        float4 vb = v4[2 + (qq >> 1)];
        float ax = (qq & 1) ? va.z : va.x;
        float ay = (qq & 1) ? va.w : va.y;
        float bx = (qq & 1) ? vb.z : vb.x;
        float by = (qq & 1) ? vb.w : vb.y;
        uint32_t h0, l0, h1, l1;
        split2(ax, ay, h0, l0);
        split2(bx, by, h1, l1);
        *reinterpret_cast<uint4*>(table + swzoff(jr, qq, ks)) = make_uint4(h0, h1, l0, l1);
    }
}

// One CTA: (b, i0..i3 = 4*ib..4*ib+3), 128 threads / 4 warps.
// A = split(E) built once; per pass p, B tables = split(W * x_i) for 2 i's;
// GEMM is pure LDS->MMA (3-term bf16 fp32 emulation).
__global__ __launch_bounds__(128, 4)
void afm_mma(const float* __restrict__ emb,
             const float* __restrict__ wW,
             const float* __restrict__ wb,
             const float* __restrict__ aW,
             float* __restrict__ outA,
             float* __restrict__ outV)
{
    extern __shared__ __align__(16) char smem[];
    const int ib  = blockIdx.x;   // 0..15
    const int b   = blockIdx.y;   // 0..255
    const int tx  = threadIdx.x;
    const int wid = tx >> 5;
    const int lid = tx & 31;
    const int g   = lid >> 2;     // 0..7
    const int q   = lid & 3;      // 0..3

    float* sWB  = reinterpret_cast<float*>(smem + OFF_WB);
    float* sAW  = reinterpret_cast<float*>(smem + OFF_AW);
    float* sLOG = reinterpret_cast<float*>(smem + OFF_LOG);
    float* sXI  = reinterpret_cast<float*>(smem + OFF_XI);

    const int jr = tx >> 1;       // row 0..63 this thread fills
    const int hf = tx & 1;        // which 32-col half

    const float* embB = emb + (size_t)b * Nn * Dn;

    if (tx < 64) {
        sWB[tx] = wb[tx];
        sAW[tx] = aW[tx];
        // natural-order copy of the CTA's 4 i-rows
        const int row = tx >> 4;
        const int c4  = tx & 15;
        reinterpret_cast<float4*>(sXI + row * 72)[c4] =
            reinterpret_cast<const float4*>(embB + (4 * ib + row) * Dn)[c4];
    }

    // ---- fill: E row -> registers + split -> sA frag table (once per CTA) ----
    float4 ereg[8];
    {
        const float4* src = reinterpret_cast<const float4*>(embB + jr * Dn + hf * 32);
        #pragma unroll
        for (int k = 0; k < 8; k++) ereg[k] = src[k];
        #pragma unroll
        for (int s = 0; s < 2; s++)
            pack_slab(smem + OFF_SA, jr, 2 * hf + s, &ereg[4 * s]);
    }
    __syncthreads();

    // ---- value writes: value[b,i,jr,:] = ereg * x_i (fp32, streaming), 4 i's ----
    #pragma unroll
    for (int L = 0; L < 4; L++) {
        const int iGlob = 4 * ib + L;
        const float4* xi = reinterpret_cast<const float4*>(sXI + L * 72 + hf * 32);
        float* oV = outV + ((((size_t)b * Nn + iGlob) * Nn + jr) * Dn + hf * 32);
        #pragma unroll
        for (int k = 0; k < 8; k++) {
            float4 x4 = xi[k];
            float4 e4 = ereg[k];
            stcs4(oV + 4 * k, make_float4(e4.x * x4.x, e4.y * x4.y, e4.z * x4.z, e4.w * x4.w));
        }
    }

    const int jb = (wid & 1) * 32 + g;             // A row base (j) for mt tiles

    #pragma unroll
    for (int p = 0; p < 2; p++) {
        // ---- build B tables: B_i[e,d] = W[e,d]*x_i[d], split, for i(2p),i(2p+1) ----
        {
            const float4* wsrc = reinterpret_cast<const float4*>(wW + jr * Dn + hf * 32);
            float4 w4[8];
            #pragma unroll
            for (int k = 0; k < 8; k++) w4[k] = wsrc[k];   // L1/L2-hot reload
            #pragma unroll
            for (int iL = 0; iL < 2; iL++) {
                const int iLocal = 2 * p + iL;
                const float4* xi = reinterpret_cast<const float4*>(sXI + iLocal * 72 + hf * 32);
                #pragma unroll
                for (int s = 0; s < 2; s++) {
                    float4 v4[4];
                    #pragma unroll
                    for (int m = 0; m < 4; m++) {
                        float4 x4 = xi[4 * s + m];
                        float4 ww = w4[4 * s + m];
                        v4[m] = make_float4(ww.x * x4.x, ww.y * x4.y, ww.z * x4.z, ww.w * x4.w);
                    }
                    pack_slab(smem + OFF_SBI + (iL << 14), jr, 2 * hf + s, v4);
                }
            }
        }
        __syncthreads();

        // ---- GEMM: pure LDS -> MMA, 3-term bf16 emulation ----
        const int iLocal = 2 * p + (wid >> 1);     // this warp's i (0..3)
        const char* sBt = smem + OFF_SBI + ((wid >> 1) << 14);

        float acc[2][8][4];
        #pragma unroll
        for (int mt = 0; mt < 2; mt++)
            #pragma unroll
            for (int nt = 0; nt < 8; nt++)
                #pragma unroll
                for (int r = 0; r < 4; r++) acc[mt][nt][r] = 0.0f;

        #pragma unroll
        for (int ks = 0; ks < 4; ks++) {
            uint32_t ah[2][4], al[2][4];
            #pragma unroll
            for (int mt = 0; mt < 2; mt++) {
                const int j0 = jb + mt * 16;
                const uint4 u0 = *reinterpret_cast<const uint4*>(
                    smem + OFF_SA + swzoff(j0,     q, ks));
                const uint4 u1 = *reinterpret_cast<const uint4*>(
                    smem + OFF_SA + swzoff(j0 + 8, q, ks));
                ah[mt][0] = u0.x; ah[mt][1] = u1.x; ah[mt][2] = u0.y; ah[mt][3] = u1.y;
                al[mt][0] = u0.z; al[mt][1] = u1.z; al[mt][2] = u0.w; al[mt][3] = u1.w;
            }
            #pragma unroll
            for (int nt = 0; nt < 8; nt++) {
                const uint4 bv = *reinterpret_cast<const uint4*>(sBt + swzoff(nt * 8 + g, q, ks));
                uint32_t bh[2] = {bv.x, bv.y};
                uint32_t bl[2] = {bv.z, bv.w};
                #pragma unroll
                for (int mt = 0; mt < 2; mt++) {
                    mma_bf16(acc[mt][nt], ah[mt], bh);
                    mma_bf16(acc[mt][nt], ah[mt], bl);
                    mma_bf16(acc[mt][nt], al[mt], bh);
                }
            }
        }

        // ---- epilogue: bias + LeakyReLU + dot(aW) -> logits ----
        float wb0[8], wb1[8], aw0[8], aw1[8];
        #pragma unroll
        for (int nt = 0; nt < 8; nt++) {
            const int e0 = nt * 8 + 2 * q;
            wb0[nt] = sWB[e0];     wb1[nt] = sWB[e0 + 1];
            aw0[nt] = sAW[e0];     aw1[nt] = sAW[e0 + 1];
        }
        #pragma unroll
        for (int mt = 0; mt < 2; mt++) {
            #pragma unroll
            for (int half = 0; half < 2; half++) {
                float pl = 0.0f;
                #pragma unroll
                for (int nt = 0; nt < 8; nt++) {
                    float q0 = acc[mt][nt][half * 2 + 0] + wb0[nt];
                    float q1 = acc[mt][nt][half * 2 + 1] + wb1[nt];
                    q0 = (q0 >= 0.0f) ? q0 : NEG_SLOPE * q0;
                    q1 = (q1 >= 0.0f) ? q1 : NEG_SLOPE * q1;
                    pl = fmaf(aw0[nt], q0, pl);
                    pl = fmaf(aw1[nt], q1, pl);
                }
                pl += __shfl_xor_sync(0xffffffffu, pl, 1);
                pl += __shfl_xor_sync(0xffffffffu, pl, 2);
                if (q == 0) {
                    const int j = (wid & 1) * 32 + mt * 16 + half * 8 + g;
                    sLOG[iLocal * 64 + j] = pl;
                }
            }
        }
        __syncthreads();
    }

    // ---- softmax per i over 64 j's: warp w -> i = 4*ib + w ----
    {
        float v0 = sLOG[wid * 64 + lid];
        float v1 = sLOG[wid * 64 + lid + 32];
        float m = fmaxf(v0, v1);
        #pragma unroll
        for (int msk = 16; msk >= 1; msk >>= 1)
            m = fmaxf(m, __shfl_xor_sync(0xffffffffu, m, msk));
        float e0 = __expf(v0 - m);
        float e1 = __expf(v1 - m);
        float s = e0 + e1;
        #pragma unroll
        for (int msk = 16; msk >= 1; msk >>= 1)
            s += __shfl_xor_sync(0xffffffffu, s, msk);
        const float inv = 1.0f / s;
        const int iGlob = 4 * ib + wid;
        float* oa = outA + ((size_t)b * Nn + iGlob) * Nn;
        oa[lid]      = e0 * inv;
        oa[lid + 32] = e1 * inv;
    }
}

extern "C" void kernel_launch(void* const* d_in, const int* in_sizes, int n_in,
                              void* d_out, int out_size)
{
    (void)in_sizes; (void)n_in; (void)out_size;
    const float* emb = (const float*)d_in[0];
    const float* wW  = (const float*)d_in[1];
    const float* wb  = (const float*)d_in[2];
    const float* aW  = (const float*)d_in[3];
    // d_in[4] = a_b: constant shift, cancels in softmax

    float* out  = (float*)d_out;
    float* outA = out;
    float* outV = out + (size_t)Bn * Nn * Nn;

    cudaFuncSetAttribute(afm_mma, cudaFuncAttributeMaxDynamicSharedMemorySize, SMEM_TOTAL);
    dim3 grid(Nn / 4, Bn);
    afm_mma<<<grid, 128, SMEM_TOTAL>>>(emb, wW, wb, aW, outA, outV);
}

// round 9
// speedup vs baseline: 1.1732x; 1.1732x over previous
#include <cuda_runtime.h>
#include <cuda_bf16.h>
#include <cstdint>

// Problem: B=256, N=64, d=64. Outputs concatenated: alphas [B,N,N,1] then value [B,N,N,64].
constexpr int Bn = 256;
constexpr int Nn = 64;
constexpr int Dn = 64;
constexpr float NEG_SLOPE = 0.01f;

// dynamic smem layout (bytes)
constexpr int OFF_WB  = 0;                       // 64 f32
constexpr int OFF_AW  = 256;                     // 64 f32
constexpr int OFF_LOG = 512;                     // 512 f32 (8 i's x 64 logits) = 2048
constexpr int OFF_XI  = 2560;                    // 8 i-rows natural fp32, stride 72: 2304
constexpr int OFF_SF  = 4992;                    // E frag table fp32 (swizzled): 16384 (128B-aligned)
constexpr int OFF_SB  = OFF_SF + 16384;          // W frag table bf16 hi/lo (swizzled): 16384
constexpr int SMEM_TOTAL = OFF_SB + 16384;       // 37760 B

static __device__ __forceinline__ void mma_bf16(float* c, const uint32_t* a, const uint32_t* b) {
    asm volatile(
        "mma.sync.aligned.m16n8k16.row.col.f32.bf16.bf16.f32 "
        "{%0,%1,%2,%3}, {%4,%5,%6,%7}, {%8,%9}, {%0,%1,%2,%3};"
        : "+f"(c[0]), "+f"(c[1]), "+f"(c[2]), "+f"(c[3])
        : "r"(a[0]), "r"(a[1]), "r"(a[2]), "r"(a[3]), "r"(b[0]), "r"(b[1]));
}

// split fp32 pair -> packed bf16x2 hi and bf16x2 lo (lo via bit-extracted hi)
static __device__ __forceinline__ void split2(float a, float b, uint32_t& hi, uint32_t& lo) {
    __nv_bfloat162 h = __floats2bfloat162_rn(a, b);
    uint32_t hu = *reinterpret_cast<uint32_t*>(&h);
    float hax = __uint_as_float(hu << 16);
    float hay = __uint_as_float(hu & 0xFFFF0000u);
    __nv_bfloat162 l = __floats2bfloat162_rn(a - hax, b - hay);
    hi = hu;
    lo = *reinterpret_cast<uint32_t*>(&l);
}

static __device__ __forceinline__ void stcs4(float* p, float4 v) {
    asm volatile("st.global.cs.v4.f32 [%0], {%1,%2,%3,%4};"
                 :: "l"(p), "f"(v.x), "f"(v.y), "f"(v.z), "f"(v.w) : "memory");
}

// swizzled byte offset of 16B unit (j*4+q) inside ks-block of a frag table.
static __device__ __forceinline__ uint32_t swzoff(int j, int q, int ks) {
    uint32_t u = (uint32_t)(j * 4 + q);
    uint32_t t = (((uint32_t)j & 3u) << 1) | (((uint32_t)ks >> 1) & 1u);
    return ((uint32_t)ks << 12) + ((u ^ t) << 4);
}

// One CTA: (b, i0..i7 = 8*ib..8*ib+7), 128 threads / 4 warps.
// Fill E fp32 frag table + W bf16 frag table once; 4 GEMM passes
// (pass p: warps 0,1 -> i(2p), warps 2,3 -> i(2p+1)) with R6's interleaved
// split2-in-loop dataflow; single barrier before softmax.
__global__ __launch_bounds__(128, 4)
void afm_mma(const float* __restrict__ emb,
             const float* __restrict__ wW,
             const float* __restrict__ wb,
             const float* __restrict__ aW,
             float* __restrict__ outA,
             float* __restrict__ outV)
{
    extern __shared__ __align__(16) char smem[];
    const int ib  = blockIdx.x;   // 0..7
    const int b   = blockIdx.y;   // 0..255
    const int tx  = threadIdx.x;
    const int wid = tx >> 5;
    const int lid = tx & 31;
    const int g   = lid >> 2;     // 0..7
    const int q   = lid & 3;      // 0..3

    float* sWB  = reinterpret_cast<float*>(smem + OFF_WB);
    float* sAW  = reinterpret_cast<float*>(smem + OFF_AW);
    float* sLOG = reinterpret_cast<float*>(smem + OFF_LOG);
    float* sXI  = reinterpret_cast<float*>(smem + OFF_XI);

    const int jr = tx >> 1;       // row 0..63 this thread fills
    const int hf = tx & 1;        // which 32-col half

    const float* embB = emb + (size_t)b * Nn * Dn;

    if (tx < 64) { sWB[tx] = wb[tx]; sAW[tx] = aW[tx]; }
    // natural-order copy of the CTA's 8 i-rows (8 rows x 16 float4)
    {
        const int row = tx >> 4;   // 0..7
        const int c4  = tx & 15;
        reinterpret_cast<float4*>(sXI + row * 72)[c4] =
            reinterpret_cast<const float4*>(embB + (8 * ib + row) * Dn)[c4];
    }

    // ---- fill: emb row -> registers + sF (swizzled fp32 frag table) ----
    float4 ereg[8];
    {
        const float4* src = reinterpret_cast<const float4*>(embB + jr * Dn + hf * 32);
        #pragma unroll
        for (int k = 0; k < 8; k++) ereg[k] = src[k];
        #pragma unroll
        for (int s = 0; s < 2; s++) {
            const int ks = 2 * hf + s;
            #pragma unroll
            for (int qq = 0; qq < 4; qq++) {
                float4 va = ereg[4 * s + (qq >> 1)];
                float4 vb = ereg[4 * s + 2 + (qq >> 1)];
                float ax = (qq & 1) ? va.z : va.x;
                float ay = (qq & 1) ? va.w : va.y;
                float bx = (qq & 1) ? vb.z : vb.x;
                float by = (qq & 1) ? vb.w : vb.y;
                *reinterpret_cast<float4*>(smem + OFF_SF + swzoff(jr, qq, ks)) =
                    make_float4(ax, ay, bx, by);
            }
        }
    }

    // ---- fill: W row -> bf16 hi/lo splits -> sB frag table (swizzled) ----
    {
        const float4* src = reinterpret_cast<const float4*>(wW + jr * Dn + hf * 32);
        uint32_t hu[16], lu[16];
        #pragma unroll
        for (int k = 0; k < 8; k++) {
            float4 w4 = src[k];
            split2(w4.x, w4.y, hu[2 * k],     lu[2 * k]);
            split2(w4.z, w4.w, hu[2 * k + 1], lu[2 * k + 1]);
        }
        #pragma unroll
        for (int s = 0; s < 2; s++) {
            const int ks = 2 * hf + s;
            #pragma unroll
            for (int qq = 0; qq < 4; qq++) {
                const int c0 = 8 * s + qq;
                *reinterpret_cast<uint4*>(smem + OFF_SB + swzoff(jr, qq, ks)) =
                    make_uint4(hu[c0], hu[c0 + 4], lu[c0], lu[c0 + 4]);
            }
        }
    }
    __syncthreads();

    // ---- value writes: value[b,i,jr,:] = ereg * x_i (fp32, streaming), 8 i's ----
    #pragma unroll
    for (int L = 0; L < 8; L++) {
        const int iGlob = 8 * ib + L;
        const float4* xi = reinterpret_cast<const float4*>(sXI + L * 72 + hf * 32);
        float* oV = outV + ((((size_t)b * Nn + iGlob) * Nn + jr) * Dn + hf * 32);
        #pragma unroll
        for (int k = 0; k < 8; k++) {
            float4 x4 = xi[k];
            float4 e4 = ereg[k];
            stcs4(oV + 4 * k, make_float4(e4.x * x4.x, e4.y * x4.y, e4.z * x4.z, e4.w * x4.w));
        }
    }

    // ---- GEMM passes: D[128x64] = (E*x_i) @ W^T, 3-term bf16 emulation ----
    const int jb = (wid & 1) * 32 + g;             // E row base (j) for mt tiles

    #pragma unroll
    for (int p = 0; p < 4; p++) {
        const int iLocal = 2 * p + (wid >> 1);     // this warp's i (0..7)
        const float* sXiN = sXI + iLocal * 72;

        float acc[2][8][4];
        #pragma unroll
        for (int mt = 0; mt < 2; mt++)
            #pragma unroll
            for (int nt = 0; nt < 8; nt++)
                #pragma unroll
                for (int r = 0; r < 4; r++) acc[mt][nt][r] = 0.0f;

        #pragma unroll
        for (int ks = 0; ks < 4; ks++) {
            const int kc = ks * 16 + 2 * q;
            const float2 xa = *reinterpret_cast<const float2*>(sXiN + kc);
            const float2 xb = *reinterpret_cast<const float2*>(sXiN + kc + 8);

            uint32_t ah[2][4], al[2][4];
            #pragma unroll
            for (int mt = 0; mt < 2; mt++) {
                const int j0 = jb + mt * 16;
                const float4 f0 = *reinterpret_cast<const float4*>(
                    smem + OFF_SF + swzoff(j0, q, ks));
                const float4 f1 = *reinterpret_cast<const float4*>(
                    smem + OFF_SF + swzoff(j0 + 8, q, ks));
                split2(f0.x * xa.x, f0.y * xa.y, ah[mt][0], al[mt][0]);
                split2(f1.x * xa.x, f1.y * xa.y, ah[mt][1], al[mt][1]);
                split2(f0.z * xb.x, f0.w * xb.y, ah[mt][2], al[mt][2]);
                split2(f1.z * xb.x, f1.w * xb.y, ah[mt][3], al[mt][3]);
            }
            #pragma unroll
            for (int nt = 0; nt < 8; nt++) {
                const uint4 bv = *reinterpret_cast<const uint4*>(
                    smem + OFF_SB + swzoff(nt * 8 + g, q, ks));
                uint32_t bh[2] = {bv.x, bv.y};
                uint32_t bl[2] = {bv.z, bv.w};
                #pragma unroll
                for (int mt = 0; mt < 2; mt++) {
                    mma_bf16(acc[mt][nt], ah[mt], bh);
                    mma_bf16(acc[mt][nt], ah[mt], bl);
                    mma_bf16(acc[mt][nt], al[mt], bh);
                }
            }
        }

        // ---- epilogue: bias + LeakyReLU + dot(aW) -> logits for this pass ----
        float wb0[8], wb1[8], aw0[8], aw1[8];
        #pragma unroll
        for (int nt = 0; nt < 8; nt++) {
            const int e0 = nt * 8 + 2 * q;
            wb0[nt] = sWB[e0];     wb1[nt] = sWB[e0 + 1];
            aw0[nt] = sAW[e0];     aw1[nt] = sAW[e0 + 1];
        }
        #pragma unroll
        for (int mt = 0; mt < 2; mt++) {
            #pragma unroll
            for (int half = 0; half < 2; half++) {
                float pl = 0.0f;
                #pragma unroll
                for (int nt = 0; nt < 8; nt++) {
                    float q0 = acc[mt][nt][half * 2 + 0] + wb0[nt];
                    float q1 = acc[mt][nt][half * 2 + 1] + wb1[nt];
                    q0 = (q0 >= 0.0f) ? q0 : NEG_SLOPE * q0;
                    q1 = (q1 >= 0.0f) ? q1 : NEG_SLOPE * q1;
                    pl = fmaf(aw0[nt], q0, pl);
                    pl = fmaf(aw1[nt], q1, pl);
                }
                pl += __shfl_xor_sync(0xffffffffu, pl, 1);
                pl += __shfl_xor_sync(0xffffffffu, pl, 2);
                if (q == 0) {
                    const int j = (wid & 1) * 32 + mt * 16 + half * 8 + g;
                    sLOG[iLocal * 64 + j] = pl;   // disjoint per pass: no barrier needed
                }
            }
        }
    }
    __syncthreads();

    // ---- softmax per i over 64 j's: warp w -> i = w and i = w+4 ----
    #pragma unroll
    for (int t = 0; t < 2; t++) {
        const int iL = wid + 4 * t;
        float v0 = sLOG[iL * 64 + lid];
        float v1 = sLOG[iL * 64 + lid + 32];
        float m = fmaxf(v0, v1);
        #pragma unroll
        for (int msk = 16; msk >= 1; msk >>= 1)
            m = fmaxf(m, __shfl_xor_sync(0xffffffffu, m, msk));
        float e0 = __expf(v0 - m);
        float e1 = __expf(v1 - m);
        float s = e0 + e1;
        #pragma unroll
        for (int msk = 16; msk >= 1; msk >>= 1)
            s += __shfl_xor_sync(0xffffffffu, s, msk);
        const float inv = 1.0f / s;
        const int iGlob = 8 * ib + iL;
        float* oa = outA + ((size_t)b * Nn + iGlob) * Nn;
        oa[lid]      = e0 * inv;
        oa[lid + 32] = e1 * inv;
    }
}

extern "C" void kernel_launch(void* const* d_in, const int* in_sizes, int n_in,
                              void* d_out, int out_size)
{
    (void)in_sizes; (void)n_in; (void)out_size;
    const float* emb = (const float*)d_in[0];
    const float* wW  = (const float*)d_in[1];
    const float* wb  = (const float*)d_in[2];
    const float* aW  = (const float*)d_in[3];
    // d_in[4] = a_b: constant shift, cancels in softmax

    float* out  = (float*)d_out;
    float* outA = out;
    float* outV = out + (size_t)Bn * Nn * Nn;

    cudaFuncSetAttribute(afm_mma, cudaFuncAttributeMaxDynamicSharedMemorySize, SMEM_TOTAL);
    dim3 grid(Nn / 8, Bn);
    afm_mma<<<grid, 128, SMEM_TOTAL>>>(emb, wW, wb, aW, outA, outV);
}

// round 10
// speedup vs baseline: 1.5690x; 1.3373x over previous
#include <cuda_runtime.h>
#include <cuda_bf16.h>
#include <cstdint>

// Problem: B=256, N=64, d=64. Outputs concatenated: alphas [B,N,N,1] then value [B,N,N,64].
constexpr int Bn = 256;
constexpr int Nn = 64;
constexpr int Dn = 64;
constexpr float NEG_SLOPE = 0.01f;

// dynamic smem layout (bytes)
constexpr int OFF_WB  = 0;                       // 64 f32
constexpr int OFF_AW  = 256;                     // 64 f32
constexpr int OFF_LOG = 512;                     // 512 f32 (8 i's x 64 logits) = 2048
constexpr int OFF_XI  = 2560;                    // 8 i-rows natural fp32, stride 72: 2304
constexpr int OFF_SF  = 4992;                    // E frag table fp32 (swizzled): 16384
constexpr int OFF_SB  = OFF_SF + 16384;          // W frag table bf16 hi/lo (swizzled): 16384
constexpr int SMEM_TOTAL = OFF_SB + 16384;       // 37760 B

static __device__ __forceinline__ void mma_bf16(float* c, const uint32_t* a, const uint32_t* b) {
    asm volatile(
        "mma.sync.aligned.m16n8k16.row.col.f32.bf16.bf16.f32 "
        "{%0,%1,%2,%3}, {%4,%5,%6,%7}, {%8,%9}, {%0,%1,%2,%3};"
        : "+f"(c[0]), "+f"(c[1]), "+f"(c[2]), "+f"(c[3])
        : "r"(a[0]), "r"(a[1]), "r"(a[2]), "r"(a[3]), "r"(b[0]), "r"(b[1]));
}

// split fp32 pair -> packed bf16x2 hi and bf16x2 lo (lo via bit-extracted hi)
static __device__ __forceinline__ void split2(float a, float b, uint32_t& hi, uint32_t& lo) {
    __nv_bfloat162 h = __floats2bfloat162_rn(a, b);
    uint32_t hu = *reinterpret_cast<uint32_t*>(&h);
    float hax = __uint_as_float(hu << 16);
    float hay = __uint_as_float(hu & 0xFFFF0000u);
    __nv_bfloat162 l = __floats2bfloat162_rn(a - hax, b - hay);
    hi = hu;
    lo = *reinterpret_cast<uint32_t*>(&l);
}

static __device__ __forceinline__ void stcs4(float* p, float4 v) {
    asm volatile("st.global.cs.v4.f32 [%0], {%1,%2,%3,%4};"
                 :: "l"(p), "f"(v.x), "f"(v.y), "f"(v.z), "f"(v.w) : "memory");
}

// swizzled byte offset of 16B unit (j*4+q) inside ks-block of a frag table.
static __device__ __forceinline__ uint32_t swzoff(int j, int q, int ks) {
    uint32_t u = (uint32_t)(j * 4 + q);
    uint32_t t = (((uint32_t)j & 3u) << 1) | (((uint32_t)ks >> 1) & 1u);
    return ((uint32_t)ks << 12) + ((u ^ t) << 4);
}

// One CTA: (b, i0..i7 = 8*ib..8*ib+7), 256 threads / 8 warps.
// Shared E fp32 frag table + W bf16 frag table filled once.
// 4 GEMM passes; pass p: warps 0-3 -> i(2p) (16 j-rows each), warps 4-7 -> i(2p+1).
// M=16 per warp => 32-reg accumulators => 3 CTAs/SM, 24 warps.
__global__ __launch_bounds__(256, 3)
void afm_mma(const float* __restrict__ emb,
             const float* __restrict__ wW,
             const float* __restrict__ wb,
             const float* __restrict__ aW,
             float* __restrict__ outA,
             float* __restrict__ outV)
{
    extern __shared__ __align__(16) char smem[];
    const int ib  = blockIdx.x;   // 0..7
    const int b   = blockIdx.y;   // 0..255
    const int tx  = threadIdx.x;
    const int wid = tx >> 5;      // 0..7
    const int lid = tx & 31;
    const int g   = lid >> 2;     // 0..7
    const int q   = lid & 3;      // 0..3

    float* sWB  = reinterpret_cast<float*>(smem + OFF_WB);
    float* sAW  = reinterpret_cast<float*>(smem + OFF_AW);
    float* sLOG = reinterpret_cast<float*>(smem + OFF_LOG);
    float* sXI  = reinterpret_cast<float*>(smem + OFF_XI);

    const int jr = tx >> 2;       // row 0..63 this thread fills
    const int qt = tx & 3;        // 16-float quarter of the row (= ks block)

    const float* embB = emb + (size_t)b * Nn * Dn;

    if (tx < 64) { sWB[tx] = wb[tx]; sAW[tx] = aW[tx]; }
    // natural-order copy of the CTA's 8 i-rows (8 rows x 16 float4 = 128 float4)
    if (tx < 128) {
        const int row = tx >> 4;   // 0..7
        const int c4  = tx & 15;
        reinterpret_cast<float4*>(sXI + row * 72)[c4] =
            reinterpret_cast<const float4*>(embB + (8 * ib + row) * Dn)[c4];
    }

    // ---- fill: emb quarter-row -> registers + sF (swizzled fp32 frag table) ----
    float4 ereg[4];
    {
        const float4* src = reinterpret_cast<const float4*>(embB + jr * Dn + qt * 16);
        #pragma unroll
        for (int k = 0; k < 4; k++) ereg[k] = src[k];
        #pragma unroll
        for (int qq = 0; qq < 4; qq++) {
            float4 va = ereg[qq >> 1];
            float4 vb = ereg[2 + (qq >> 1)];
            float ax = (qq & 1) ? va.z : va.x;
            float ay = (qq & 1) ? va.w : va.y;
            float bx = (qq & 1) ? vb.z : vb.x;
            float by = (qq & 1) ? vb.w : vb.y;
            *reinterpret_cast<float4*>(smem + OFF_SF + swzoff(jr, qq, qt)) =
                make_float4(ax, ay, bx, by);
        }
    }

    // ---- fill: W quarter-row -> bf16 hi/lo splits -> sB frag table (swizzled) ----
    {
        const float4* src = reinterpret_cast<const float4*>(wW + jr * Dn + qt * 16);
        uint32_t hu[8], lu[8];
        #pragma unroll
        for (int k = 0; k < 4; k++) {
            float4 w4 = src[k];
            split2(w4.x, w4.y, hu[2 * k],     lu[2 * k]);
            split2(w4.z, w4.w, hu[2 * k + 1], lu[2 * k + 1]);
        }
        #pragma unroll
        for (int qq = 0; qq < 4; qq++) {
            *reinterpret_cast<uint4*>(smem + OFF_SB + swzoff(jr, qq, qt)) =
                make_uint4(hu[qq], hu[qq + 4], lu[qq], lu[qq + 4]);
        }
    }
    __syncthreads();

    // ---- value writes: value[b,i,jr,qt*16..] = ereg * x_i (fp32, streaming), 8 i's ----
    #pragma unroll
    for (int L = 0; L < 8; L++) {
        const int iGlob = 8 * ib + L;
        const float4* xi = reinterpret_cast<const float4*>(sXI + L * 72 + qt * 16);
        float* oV = outV + ((((size_t)b * Nn + iGlob) * Nn + jr) * Dn + qt * 16);
        #pragma unroll
        for (int k = 0; k < 4; k++) {
            float4 x4 = xi[k];
            float4 e4 = ereg[k];
            stcs4(oV + 4 * k, make_float4(e4.x * x4.x, e4.y * x4.y, e4.z * x4.z, e4.w * x4.w));
        }
    }

    // ---- GEMM passes: per i, D[64x64] = (E*x_i) @ W^T, 3-term bf16 emulation ----
    const int jw = (wid & 3) * 16;                 // this warp's 16 j-rows

    #pragma unroll
    for (int p = 0; p < 4; p++) {
        const int iLocal = 2 * p + (wid >> 2);     // this warp's i (0..7)
        const float* sXiN = sXI + iLocal * 72;

        float acc[8][4];
        #pragma unroll
        for (int nt = 0; nt < 8; nt++)
            #pragma unroll
            for (int r = 0; r < 4; r++) acc[nt][r] = 0.0f;

        #pragma unroll
        for (int ks = 0; ks < 4; ks++) {
            const int kc = ks * 16 + 2 * q;
            const float2 xa = *reinterpret_cast<const float2*>(sXiN + kc);
            const float2 xb = *reinterpret_cast<const float2*>(sXiN + kc + 8);

            uint32_t ah[4], al[4];
            {
                const float4 f0 = *reinterpret_cast<const float4*>(
                    smem + OFF_SF + swzoff(jw + g, q, ks));
                const float4 f1 = *reinterpret_cast<const float4*>(
                    smem + OFF_SF + swzoff(jw + g + 8, q, ks));
                split2(f0.x * xa.x, f0.y * xa.y, ah[0], al[0]);
                split2(f1.x * xa.x, f1.y * xa.y, ah[1], al[1]);
                split2(f0.z * xb.x, f0.w * xb.y, ah[2], al[2]);
                split2(f1.z * xb.x, f1.w * xb.y, ah[3], al[3]);
            }
            #pragma unroll
            for (int nt = 0; nt < 8; nt++) {
                const uint4 bv = *reinterpret_cast<const uint4*>(
                    smem + OFF_SB + swzoff(nt * 8 + g, q, ks));
                uint32_t bh[2] = {bv.x, bv.y};
                uint32_t bl[2] = {bv.z, bv.w};
                mma_bf16(acc[nt], ah, bh);
                mma_bf16(acc[nt], ah, bl);
                mma_bf16(acc[nt], al, bh);
            }
        }

        // ---- epilogue: bias + LeakyReLU + dot(aW) -> logits for this pass ----
        #pragma unroll
        for (int half = 0; half < 2; half++) {
            float pl = 0.0f;
            #pragma unroll
            for (int nt = 0; nt < 8; nt++) {
                const int e0 = nt * 8 + 2 * q;
                float q0 = acc[nt][half * 2 + 0] + sWB[e0];
                float q1 = acc[nt][half * 2 + 1] + sWB[e0 + 1];
                q0 = (q0 >= 0.0f) ? q0 : NEG_SLOPE * q0;
                q1 = (q1 >= 0.0f) ? q1 : NEG_SLOPE * q1;
                pl = fmaf(sAW[e0], q0, pl);
                pl = fmaf(sAW[e0 + 1], q1, pl);
            }
            pl += __shfl_xor_sync(0xffffffffu, pl, 1);
            pl += __shfl_xor_sync(0xffffffffu, pl, 2);
            if (q == 0) sLOG[iLocal * 64 + jw + half * 8 + g] = pl;  // disjoint per pass
        }
    }
    __syncthreads();

    // ---- softmax per i over 64 j's: warp w -> i = w ----
    {
        const int iL = wid;
        float v0 = sLOG[iL * 64 + lid];
        float v1 = sLOG[iL * 64 + lid + 32];
        float m = fmaxf(v0, v1);
        #pragma unroll
        for (int msk = 16; msk >= 1; msk >>= 1)
            m = fmaxf(m, __shfl_xor_sync(0xffffffffu, m, msk));
        float e0 = __expf(v0 - m);
        float e1 = __expf(v1 - m);
        float s = e0 + e1;
        #pragma unroll
        for (int msk = 16; msk >= 1; msk >>= 1)
            s += __shfl_xor_sync(0xffffffffu, s, msk);
        const float inv = 1.0f / s;
        const int iGlob = 8 * ib + iL;
        float* oa = outA + ((size_t)b * Nn + iGlob) * Nn;
        oa[lid]      = e0 * inv;
        oa[lid + 32] = e1 * inv;
    }
}

extern "C" void kernel_launch(void* const* d_in, const int* in_sizes, int n_in,
                              void* d_out, int out_size)
{
    (void)in_sizes; (void)n_in; (void)out_size;
    const float* emb = (const float*)d_in[0];
    const float* wW  = (const float*)d_in[1];
    const float* wb  = (const float*)d_in[2];
    const float* aW  = (const float*)d_in[3];
    // d_in[4] = a_b: constant shift, cancels in softmax

    float* out  = (float*)d_out;
    float* outA = out;
    float* outV = out + (size_t)Bn * Nn * Nn;

    cudaFuncSetAttribute(afm_mma, cudaFuncAttributeMaxDynamicSharedMemorySize, SMEM_TOTAL);
    dim3 grid(Nn / 8, Bn);
    afm_mma<<<grid, 256, SMEM_TOTAL>>>(emb, wW, wb, aW, outA, outV);
}